// round 12
// baseline (speedup 1.0000x reference)
#include <cuda_runtime.h>
#include <math.h>

#define Bv  8
#define Tv  32
#define Nv  500
#define Fv  64
#define Hv  128
#define Ev  8000
#define BT  256            // B*T
#define BTN 128000         // B*T*N
#define NNZ (Ev + Nv)

// ---------------- scratch (static device globals: allowed) ----------------
__device__ float  g_xf [BTN * Hv];   // x @ W_gcn            (bt, n, h)
__device__ float  g_res[BTN * Hv];   // x @ W_res + b_res    (bt, n, h)
__device__ float  g_hg [BTN * Hv];   // gelu(gcn agg + b)    (bt, n, h)
__device__ float  g_wt [384 * Hv];   // W_temp transposed: [(i*3+k)][o]
__device__ float  g_deg [Nv];
__device__ float  g_dinv[Nv];
__device__ int    g_cnt [Nv];
__device__ int    g_rowptr[Nv + 1];
__device__ int    g_fill[Nv];
__device__ float2 g_ev[NNZ];         // {norm, __int_as_float(src)} CSR by dst
__device__ int    g_is64;            // edge_index dtype flag

// ---------------- helpers ----------------
__device__ __forceinline__ unsigned long long pack2(float lo, float hi) {
    unsigned long long r;
    asm("mov.b64 %0, {%1, %2};" : "=l"(r) : "f"(lo), "f"(hi));
    return r;
}
__device__ __forceinline__ void unpack2(unsigned long long v, float& lo, float& hi) {
    asm("mov.b64 {%0, %1}, %2;" : "=f"(lo), "=f"(hi) : "l"(v));
}
__device__ __forceinline__ void fma2(unsigned long long& d, unsigned long long a,
                                     unsigned long long b) {
    asm("fma.rn.f32x2 %0, %1, %2, %0;" : "+l"(d) : "l"(a), "l"(b));
}
__device__ __forceinline__ float gelu_exact(float x) {
    return 0.5f * x * (1.0f + erff(x * 0.7071067811865476f));
}
__device__ __forceinline__ int load_idx(const void* ei, int i) {
    long long v;
    if (g_is64) v = ((const long long*)ei)[i];
    else        v = ((const int*)ei)[i];
    if (v < 0) v = 0;
    if (v >= Nv) v = Nv - 1;
    return (int)v;
}

// ---------------- P0: dtype detect + zero counters ----------------
__global__ void p_start(const void* __restrict__ ei) {
    int i = threadIdx.x;
    if (i == 0) {
        const long long* p = (const long long*)ei;
        int ok64 = 1;
        for (int j = 0; j < 8; ++j) {
            long long v = p[j];
            if (v < 0 || v >= Nv) ok64 = 0;
        }
        g_is64 = ok64;
    }
    if (i < Nv) { g_deg[i] = 0.0f; g_cnt[i] = 0; }
}

// ---------------- P1: degree + counts; extra blocks transpose W_temp ------
__global__ void p_deg(const void* __restrict__ ei, const float* __restrict__ ew,
                      const float* __restrict__ Wt) {
    if (blockIdx.x >= 63) {
        int idx = (blockIdx.x - 63) * 128 + threadIdx.x;   // < 49152
        if (idx < 128 * 384) {
            int o = idx / 384, m = idx % 384;
            g_wt[m * Hv + o] = Wt[o * 384 + m];
        }
        return;
    }
    int e = blockIdx.x * 128 + threadIdx.x;
    if (e >= Ev) return;
    int dst = load_idx(ei, Ev + e);
    atomicAdd(&g_deg[dst], ew[e]);
    atomicAdd(&g_cnt[dst], 1);
}

// ---------------- P2: dinv + prefix scan -> rowptr/fill ----------------
__global__ void p_scan() {
    __shared__ int s[512];
    int tid = threadIdx.x;
    int c = 0;
    if (tid < Nv) {
        float d = g_deg[tid] + 1.0f;           // + self loop weight
        g_dinv[tid] = rsqrtf(d);
        c = g_cnt[tid] + 1;                    // + self loop edge
    }
    s[tid] = c;
    __syncthreads();
    for (int off = 1; off < 512; off <<= 1) {
        int v = (tid >= off) ? s[tid - off] : 0;
        __syncthreads();
        s[tid] += v;
        __syncthreads();
    }
    if (tid < Nv) {
        g_rowptr[tid + 1] = s[tid];
        g_fill[tid] = s[tid] - c;
        if (tid == 0) g_rowptr[0] = 0;
    }
}

// ---------------- P3: CSR fill with normalized edge values ----------------
__global__ void p_fill(const void* __restrict__ ei, const float* __restrict__ ew) {
    int e = blockIdx.x * blockDim.x + threadIdx.x;
    if (e >= NNZ) return;
    int src, dst; float w;
    if (e < Ev) { src = load_idx(ei, e); dst = load_idx(ei, Ev + e); w = ew[e]; }
    else        { src = dst = e - Ev; w = 1.0f; }
    float v = g_dinv[src] * w * g_dinv[dst];
    int pos = atomicAdd(&g_fill[dst], 1);
    if (pos >= 0 && pos < NNZ)
        g_ev[pos] = make_float2(v, __int_as_float(src));
}

// ---------------- K2: input projection, row-pair f32x2, two grid.y passes -
// y=0: x @ W_gcn -> g_xf (no bias);  y=1: x @ W_res + br -> g_res
__global__ __launch_bounds__(128) void k_inproj(
    const float* __restrict__ x, const float* __restrict__ Wg,
    const float* __restrict__ Wr, const float* __restrict__ br) {
    __shared__ __align__(16) float2 sxp[4 * 64];   // [pair][i]
    int h = threadIdx.x;
    const float* W = blockIdx.y ? Wr : Wg;
    float* dst = blockIdx.y ? g_res : g_xf;
    float bb = blockIdx.y ? br[h] : 0.0f;
    float w[64];
#pragma unroll
    for (int i = 0; i < 64; ++i) w[i] = W[i * Hv + h];
    int row0 = blockIdx.x * 128;
#pragma unroll 1
    for (int c = 0; c < 16; ++c) {
        int rbase = row0 + c * 8;
        __syncthreads();
        for (int idx = h; idx < 512; idx += 128) {
            int rr = idx >> 6, cc = idx & 63;
            float v = x[(rbase + rr) * Fv + cc];
            ((float*)sxp)[((rr >> 1) * 64 + cc) * 2 + (rr & 1)] = v;
        }
        __syncthreads();
        unsigned long long acc0 = 0ULL, acc1 = 0ULL, acc2 = 0ULL, acc3 = 0ULL;
#pragma unroll
        for (int i = 0; i < 64; i += 2) {
            ulonglong2 v0 = *(const ulonglong2*)&sxp[0 * 64 + i];
            ulonglong2 v1 = *(const ulonglong2*)&sxp[1 * 64 + i];
            ulonglong2 v2 = *(const ulonglong2*)&sxp[2 * 64 + i];
            ulonglong2 v3 = *(const ulonglong2*)&sxp[3 * 64 + i];
            unsigned long long w0 = pack2(w[i], w[i]);
            unsigned long long w1 = pack2(w[i + 1], w[i + 1]);
            fma2(acc0, v0.x, w0); fma2(acc0, v0.y, w1);
            fma2(acc1, v1.x, w0); fma2(acc1, v1.y, w1);
            fma2(acc2, v2.x, w0); fma2(acc2, v2.y, w1);
            fma2(acc3, v3.x, w0); fma2(acc3, v3.y, w1);
        }
        float a0, a1;
        unpack2(acc0, a0, a1);
        dst[(rbase + 0) * Hv + h] = a0 + bb;
        dst[(rbase + 1) * Hv + h] = a1 + bb;
        unpack2(acc1, a0, a1);
        dst[(rbase + 2) * Hv + h] = a0 + bb;
        dst[(rbase + 3) * Hv + h] = a1 + bb;
        unpack2(acc2, a0, a1);
        dst[(rbase + 4) * Hv + h] = a0 + bb;
        dst[(rbase + 5) * Hv + h] = a1 + bb;
        unpack2(acc3, a0, a1);
        dst[(rbase + 6) * Hv + h] = a0 + bb;
        dst[(rbase + 7) * Hv + h] = a1 + bb;
    }
}

// ---------------- K3: GCN aggregate + bias + gelu ----------------
// 16 channels per block as 8 float2 pairs; SAME 32KB smem as R4 (occupancy
// preserved) but half the serial edge chain per thread + f32x2 math.
__global__ __launch_bounds__(128) void k_gcn(const float* __restrict__ bg) {
    __shared__ __align__(16) float2 sxf2[Nv * 8];   // 32000 B
    int bt = blockIdx.x;
    int hbase = blockIdx.y * 16;
    int tid = threadIdx.x;
    const float2* xsrc2 = (const float2*)(g_xf + (size_t)bt * (Nv * Hv));
    int c2base = hbase >> 1;
    for (int idx = tid; idx < Nv * 8; idx += 128) {
        int n = idx >> 3, c2 = idx & 7;
        sxf2[idx] = xsrc2[n * 64 + c2base + c2];
    }
    __syncthreads();
    int hh2 = tid & 7;               // channel pair within tile
    int ns = tid >> 3;               // 0..15
    int ch = hbase + 2 * hh2;
    float bg0 = bg[ch], bg1 = bg[ch + 1];
    float2* dst2 = (float2*)(g_hg + (size_t)bt * (Nv * Hv));
    const unsigned long long* sxp = (const unsigned long long*)sxf2;
    for (int n = ns; n < Nv; n += 16) {
        int rs = g_rowptr[n], re = g_rowptr[n + 1];
        unsigned long long acc = 0ULL;
        int e = rs;
        for (; e + 1 < re; e += 2) {
            float2 ev0 = g_ev[e];
            float2 ev1 = g_ev[e + 1];
            fma2(acc, pack2(ev0.x, ev0.x), sxp[__float_as_int(ev0.y) * 8 + hh2]);
            fma2(acc, pack2(ev1.x, ev1.x), sxp[__float_as_int(ev1.y) * 8 + hh2]);
        }
        if (e < re) {
            float2 ev0 = g_ev[e];
            fma2(acc, pack2(ev0.x, ev0.x), sxp[__float_as_int(ev0.y) * 8 + hh2]);
        }
        float a0, a1; unpack2(acc, a0, a1);
        dst2[n * 64 + (ch >> 1)] =
            make_float2(gelu_exact(a0 + bg0), gelu_exact(a1 + bg1));
    }
}

// ---------------- K4: temporal conv(K=3) + gelu + residual + LayerNorm ----
// v4 (R11 best): ONE (b,n) per block; t-dim packed into f32x2 lanes (t, t+16).
__global__ __launch_bounds__(128) void k_conv(
    const float* __restrict__ btmp,
    const float* __restrict__ lnw, const float* __restrict__ lnb,
    float* __restrict__ out) {
    __shared__ __align__(16) char smbuf[18432];
    __shared__ float smu[32], srs[32];
    int o = threadIdx.x;
    int bn = blockIdx.x;
    int b = bn / Nv, n = bn % Nv;

    // ---- stage packed input pairs ----
    {
        float xv[32];
        const float* src = g_hg + ((size_t)(b * Tv) * Nv + n) * Hv + o;
#pragma unroll
        for (int t = 0; t < 32; ++t) xv[t] = src[(size_t)t * Nv * Hv];
        float2* sp = (float2*)smbuf;          // [s][128]
#pragma unroll
        for (int s = 0; s < 18; ++s) {
            float lo = (s == 0)  ? 0.0f : xv[s - 1];
            float hi = (s == 17) ? 0.0f : xv[s + 15];
            sp[s * 128 + o] = make_float2(lo, hi);
        }
    }
    __syncthreads();

    unsigned long long acc[16];
#pragma unroll
    for (int t = 0; t < 16; ++t) acc[t] = 0ULL;

    const float* wtp = g_wt + o;               // [(m)][o], lane-coalesced
    const ulonglong2* colbase = (const ulonglong2*)smbuf;   // [s][64]
#pragma unroll 1
    for (int q = 0; q < 64; ++q) {             // i = 2q, 2q+1
        int m = q * 6;
        float wa0 = wtp[(m + 0) * Hv];
        float wa1 = wtp[(m + 1) * Hv];
        float wa2 = wtp[(m + 2) * Hv];
        float wb0 = wtp[(m + 3) * Hv];
        float wb1 = wtp[(m + 4) * Hv];
        float wb2 = wtp[(m + 5) * Hv];
        unsigned long long w0a = pack2(wa0, wa0), w1a = pack2(wa1, wa1),
                           w2a = pack2(wa2, wa2);
        unsigned long long w0b = pack2(wb0, wb0), w1b = pack2(wb1, wb1),
                           w2b = pack2(wb2, wb2);
        const ulonglong2* col = colbase + q;    // stride 64 per s
        ulonglong2 v0 = col[0];                 // s = t + kk
        ulonglong2 v1 = col[64];
#pragma unroll
        for (int t = 0; t < 16; ++t) {
            ulonglong2 v2 = col[(t + 2) * 64];
            fma2(acc[t], w0a, v0.x);
            fma2(acc[t], w0b, v0.y);
            fma2(acc[t], w1a, v1.x);
            fma2(acc[t], w1b, v1.y);
            fma2(acc[t], w2a, v2.x);
            fma2(acc[t], w2b, v2.y);
            v0 = v1; v1 = v2;
        }
    }
    __syncthreads();   // done reading p; reuse smbuf as y[32][129]

    float btv = btmp[o];
    float* shy = (float*)smbuf;
    {
        const float* resp = g_res + ((size_t)(b * Tv) * Nv + n) * Hv + o;
#pragma unroll
        for (int t = 0; t < 16; ++t) {
            float y0, y1; unpack2(acc[t], y0, y1);
            float h0 = gelu_exact(y0 + btv) + resp[(size_t)t * Nv * Hv];
            float h1 = gelu_exact(y1 + btv) + resp[(size_t)(t + 16) * Nv * Hv];
            shy[t * 129 + o] = h0;
            shy[(t + 16) * 129 + o] = h1;
        }
    }
    __syncthreads();

    if (o < 32) {
        int r = o;
        float s1 = 0.0f;
#pragma unroll 8
        for (int j = 0; j < 128; ++j) s1 += shy[r * 129 + j];
        float mu = s1 * (1.0f / 128.0f);
        float s2 = 0.0f;
#pragma unroll 8
        for (int j = 0; j < 128; ++j) {
            float d = shy[r * 129 + j] - mu;
            s2 += d * d;
        }
        smu[r] = mu;
        srs[r] = rsqrtf(s2 * (1.0f / 128.0f) + 1e-5f);
    }
    __syncthreads();

    float lw = lnw[o], lb = lnb[o];
    float* op = out + ((size_t)(b * Tv) * Nv + n) * Hv + o;
#pragma unroll
    for (int t = 0; t < 32; ++t) {
        float v = shy[t * 129 + o];
        op[(size_t)t * Nv * Hv] = (v - smu[t]) * srs[t] * lw + lb;
    }
}

// ---------------- launch ----------------
extern "C" void kernel_launch(void* const* d_in, const int* in_sizes, int n_in,
                              void* d_out, int out_size) {
    const float* x   = (const float*)d_in[0];
    const void*  ei  = d_in[1];
    const float* ew  = (const float*)d_in[2];
    const float* Wg  = (const float*)d_in[3];
    const float* bg  = (const float*)d_in[4];
    const float* Wt  = (const float*)d_in[5];
    const float* btm = (const float*)d_in[6];
    const float* lnw = (const float*)d_in[7];
    const float* lnb = (const float*)d_in[8];
    const float* Wr  = (const float*)d_in[9];
    const float* br  = (const float*)d_in[10];
    float* out = (float*)d_out;

    p_start<<<1, 512>>>(ei);
    p_deg <<<63 + 384, 128>>>(ei, ew, Wt);
    p_scan<<<1, 512>>>();
    p_fill<<<(NNZ + 127) / 128, 128>>>(ei, ew);
    k_inproj<<<dim3(1000, 2), 128>>>(x, Wg, Wr, br);
    k_gcn<<<dim3(BT, 8), 128>>>(bg);
    k_conv<<<4000, 128>>>(btm, lnw, lnb, out);
}

// round 13
// speedup vs baseline: 1.0113x; 1.0113x over previous
#include <cuda_runtime.h>
#include <math.h>

#define Bv  8
#define Tv  32
#define Nv  500
#define Fv  64
#define Hv  128
#define Ev  8000
#define BT  256            // B*T
#define BTN 128000         // B*T*N
#define NNZ (Ev + Nv)

// ---------------- scratch (static device globals: allowed) ----------------
__device__ float  g_xf [BTN * Hv];   // x @ W_gcn            (bt, n, h)
__device__ float  g_res[BTN * Hv];   // x @ W_res + b_res    (bt, n, h)
__device__ float  g_hg [BTN * Hv];   // gelu(gcn agg + b)    (bt, n, h)
__device__ float  g_wt [384 * Hv];   // W_temp transposed: [(i*3+k)][o]
__device__ float  g_deg [Nv];        // zero-init (BSS); re-zeroed each run
__device__ int    g_cnt [Nv];        // zero-init (BSS); re-zeroed each run
__device__ int    g_rowptr[Nv + 1];
__device__ float2 g_ev[NNZ];         // {norm, __int_as_float(src)} CSR by dst

// ---------------- helpers ----------------
__device__ __forceinline__ unsigned long long pack2(float lo, float hi) {
    unsigned long long r;
    asm("mov.b64 %0, {%1, %2};" : "=l"(r) : "f"(lo), "f"(hi));
    return r;
}
__device__ __forceinline__ void unpack2(unsigned long long v, float& lo, float& hi) {
    asm("mov.b64 {%0, %1}, %2;" : "=f"(lo), "=f"(hi) : "l"(v));
}
__device__ __forceinline__ void fma2(unsigned long long& d, unsigned long long a,
                                     unsigned long long b) {
    asm("fma.rn.f32x2 %0, %1, %2, %0;" : "+l"(d) : "l"(a), "l"(b));
}
__device__ __forceinline__ float gelu_exact(float x) {
    return 0.5f * x * (1.0f + erff(x * 0.7071067811865476f));
}
__device__ __forceinline__ int detect64(const void* ei) {
    const long long* p = (const long long*)ei;
    int ok64 = 1;
#pragma unroll
    for (int j = 0; j < 8; ++j) {
        long long v = p[j];
        if (v < 0 || v >= Nv) ok64 = 0;
    }
    return ok64;
}
__device__ __forceinline__ int load_idx(const void* ei, int i, int is64) {
    long long v;
    if (is64) v = ((const long long*)ei)[i];
    else      v = ((const int*)ei)[i];
    if (v < 0) v = 0;
    if (v >= Nv) v = Nv - 1;
    return (int)v;
}

// ---------------- K2 (launch #1): fused input projections, f32x2 packed ---
__global__ __launch_bounds__(128) void k_inproj(
    const float* __restrict__ x, const float* __restrict__ Wg,
    const float* __restrict__ Wr, const float* __restrict__ br) {
    __shared__ float sx[8][64];
    int h = threadIdx.x;
    unsigned long long wp[64];
#pragma unroll
    for (int i = 0; i < 64; ++i) wp[i] = pack2(Wg[i * Hv + h], Wr[i * Hv + h]);
    float brh = br[h];
    int row0 = blockIdx.x * 128;
#pragma unroll 1
    for (int c = 0; c < 16; ++c) {
        int rbase = row0 + c * 8;
        __syncthreads();
        for (int j = h; j < 512; j += 128)
            sx[j >> 6][j & 63] = x[(rbase + (j >> 6)) * Fv + (j & 63)];
        __syncthreads();
#pragma unroll
        for (int r = 0; r < 8; ++r) {
            unsigned long long acc = 0ULL;
#pragma unroll
            for (int i = 0; i < 64; i += 4) {
                float4 xv = *(const float4*)&sx[r][i];
                fma2(acc, pack2(xv.x, xv.x), wp[i + 0]);
                fma2(acc, pack2(xv.y, xv.y), wp[i + 1]);
                fma2(acc, pack2(xv.z, xv.z), wp[i + 2]);
                fma2(acc, pack2(xv.w, xv.w), wp[i + 3]);
            }
            float ag, ar; unpack2(acc, ag, ar);
            int row = rbase + r;
            g_xf [row * Hv + h] = ag;
            g_res[row * Hv + h] = ar + brh;
        }
    }
}

// ---------------- P1 (launch #2): degree + counts; tail blocks wtrans -----
__global__ void p_deg(const void* __restrict__ ei, const float* __restrict__ ew,
                      const float* __restrict__ Wt) {
    if (blockIdx.x >= 63) {
        int idx = (blockIdx.x - 63) * 128 + threadIdx.x;   // < 49152
        if (idx < 128 * 384) {
            int o = idx / 384, m = idx % 384;
            g_wt[m * Hv + o] = Wt[o * 384 + m];
        }
        return;
    }
    __shared__ int sis64;
    if (threadIdx.x == 0) sis64 = detect64(ei);
    __syncthreads();
    int is64 = sis64;
    int e = blockIdx.x * 128 + threadIdx.x;
    if (e >= Ev) return;
    int dst = load_idx(ei, Ev + e, is64);
    atomicAdd(&g_deg[dst], ew[e]);
    atomicAdd(&g_cnt[dst], 1);
}

// ---------------- P2 (launch #3): scan + CSR fill, single block -----------
__global__ __launch_bounds__(512) void p_scanfill(
    const void* __restrict__ ei, const float* __restrict__ ew) {
    __shared__ int   s[512];
    __shared__ float sdinv[Nv];
    __shared__ int   sfill[Nv];
    __shared__ int   sis64;
    int tid = threadIdx.x;
    if (tid == 0) sis64 = detect64(ei);

    int c = 0;
    if (tid < Nv) {
        float d = g_deg[tid] + 1.0f;           // + self loop weight
        sdinv[tid] = rsqrtf(d);
        c = g_cnt[tid] + 1;                    // + self loop edge
    }
    s[tid] = c;
    __syncthreads();
    for (int off = 1; off < 512; off <<= 1) {
        int v = (tid >= off) ? s[tid - off] : 0;
        __syncthreads();
        s[tid] += v;
        __syncthreads();
    }
    if (tid < Nv) {
        g_rowptr[tid + 1] = s[tid];
        sfill[tid] = s[tid] - c;
        if (tid == 0) g_rowptr[0] = 0;
        g_deg[tid] = 0.0f;                     // reset for next graph replay
        g_cnt[tid] = 0;
    }
    __syncthreads();
    int is64 = sis64;
    for (int e = tid; e < NNZ; e += 512) {
        int src, dst; float w;
        if (e < Ev) { src = load_idx(ei, e, is64); dst = load_idx(ei, Ev + e, is64); w = ew[e]; }
        else        { src = dst = e - Ev; w = 1.0f; }
        float v = sdinv[src] * w * sdinv[dst];
        int pos = atomicAdd(&sfill[dst], 1);
        if (pos >= 0 && pos < NNZ)
            g_ev[pos] = make_float2(v, __int_as_float(src));
    }
}

// ---------------- K3 (launch #4, PROFILED): GCN aggregate + bias + gelu ---
__global__ __launch_bounds__(128) void k_gcn(const float* __restrict__ bg) {
    __shared__ float sxf[Nv * 16];
    int bt = blockIdx.x;
    int hbase = blockIdx.y * 16;
    int tid = threadIdx.x;
    const float* xsrc = g_xf + bt * (Nv * Hv);
    for (int idx = tid; idx < Nv * 16; idx += 128) {
        int n = idx >> 4, hh = idx & 15;
        sxf[idx] = xsrc[n * Hv + hbase + hh];
    }
    __syncthreads();
    int hh = tid & 15;
    int ns = tid >> 4;
    float bgv = bg[hbase + hh];
    float* dst = g_hg + bt * (Nv * Hv);
    for (int n = ns; n < Nv; n += 8) {
        int rs = g_rowptr[n], re = g_rowptr[n + 1];
        float acc = 0.0f;
        int e = rs;
        for (; e + 1 < re; e += 2) {
            float2 ev0 = g_ev[e];
            float2 ev1 = g_ev[e + 1];
            acc += ev0.x * sxf[__float_as_int(ev0.y) * 16 + hh];
            acc += ev1.x * sxf[__float_as_int(ev1.y) * 16 + hh];
        }
        if (e < re) {
            float2 ev0 = g_ev[e];
            acc += ev0.x * sxf[__float_as_int(ev0.y) * 16 + hh];
        }
        dst[n * Hv + hbase + hh] = gelu_exact(acc + bgv);
    }
}

// ---------------- K4 (launch #5): conv + gelu + residual + LayerNorm ------
// v4 (R11 best): ONE (b,n) per block; t-dim packed into f32x2 lanes (t, t+16).
__global__ __launch_bounds__(128) void k_conv(
    const float* __restrict__ btmp,
    const float* __restrict__ lnw, const float* __restrict__ lnb,
    float* __restrict__ out) {
    __shared__ __align__(16) char smbuf[18432];
    __shared__ float smu[32], srs[32];
    int o = threadIdx.x;
    int bn = blockIdx.x;
    int b = bn / Nv, n = bn % Nv;

    // ---- stage packed input pairs ----
    {
        float xv[32];
        const float* src = g_hg + ((size_t)(b * Tv) * Nv + n) * Hv + o;
#pragma unroll
        for (int t = 0; t < 32; ++t) xv[t] = src[(size_t)t * Nv * Hv];
        float2* sp = (float2*)smbuf;          // [s][128]
#pragma unroll
        for (int s = 0; s < 18; ++s) {
            float lo = (s == 0)  ? 0.0f : xv[s - 1];
            float hi = (s == 17) ? 0.0f : xv[s + 15];
            sp[s * 128 + o] = make_float2(lo, hi);
        }
    }
    __syncthreads();

    unsigned long long acc[16];
#pragma unroll
    for (int t = 0; t < 16; ++t) acc[t] = 0ULL;

    const float* wtp = g_wt + o;               // [(m)][o], lane-coalesced
    const ulonglong2* colbase = (const ulonglong2*)smbuf;   // [s][64]
#pragma unroll 1
    for (int q = 0; q < 64; ++q) {             // i = 2q, 2q+1
        int m = q * 6;
        float wa0 = wtp[(m + 0) * Hv];
        float wa1 = wtp[(m + 1) * Hv];
        float wa2 = wtp[(m + 2) * Hv];
        float wb0 = wtp[(m + 3) * Hv];
        float wb1 = wtp[(m + 4) * Hv];
        float wb2 = wtp[(m + 5) * Hv];
        unsigned long long w0a = pack2(wa0, wa0), w1a = pack2(wa1, wa1),
                           w2a = pack2(wa2, wa2);
        unsigned long long w0b = pack2(wb0, wb0), w1b = pack2(wb1, wb1),
                           w2b = pack2(wb2, wb2);
        const ulonglong2* col = colbase + q;    // stride 64 per s
        ulonglong2 v0 = col[0];                 // s = t + kk
        ulonglong2 v1 = col[64];
#pragma unroll
        for (int t = 0; t < 16; ++t) {
            ulonglong2 v2 = col[(t + 2) * 64];
            fma2(acc[t], w0a, v0.x);
            fma2(acc[t], w0b, v0.y);
            fma2(acc[t], w1a, v1.x);
            fma2(acc[t], w1b, v1.y);
            fma2(acc[t], w2a, v2.x);
            fma2(acc[t], w2b, v2.y);
            v0 = v1; v1 = v2;
        }
    }
    __syncthreads();   // done reading p; reuse smbuf as y[32][129]

    float btv = btmp[o];
    float* shy = (float*)smbuf;
    {
        const float* resp = g_res + ((size_t)(b * Tv) * Nv + n) * Hv + o;
#pragma unroll
        for (int t = 0; t < 16; ++t) {
            float y0, y1; unpack2(acc[t], y0, y1);
            float h0 = gelu_exact(y0 + btv) + resp[(size_t)t * Nv * Hv];
            float h1 = gelu_exact(y1 + btv) + resp[(size_t)(t + 16) * Nv * Hv];
            shy[t * 129 + o] = h0;
            shy[(t + 16) * 129 + o] = h1;
        }
    }
    __syncthreads();

    if (o < 32) {
        int r = o;
        float s1 = 0.0f;
#pragma unroll 8
        for (int j = 0; j < 128; ++j) s1 += shy[r * 129 + j];
        float mu = s1 * (1.0f / 128.0f);
        float s2 = 0.0f;
#pragma unroll 8
        for (int j = 0; j < 128; ++j) {
            float d = shy[r * 129 + j] - mu;
            s2 += d * d;
        }
        smu[r] = mu;
        srs[r] = rsqrtf(s2 * (1.0f / 128.0f) + 1e-5f);
    }
    __syncthreads();

    float lw = lnw[o], lb = lnb[o];
    float* op = out + ((size_t)(b * Tv) * Nv + n) * Hv + o;
#pragma unroll
    for (int t = 0; t < 32; ++t) {
        float v = shy[t * 129 + o];
        op[(size_t)t * Nv * Hv] = (v - smu[t]) * srs[t] * lw + lb;
    }
}

// ---------------- launch ----------------
extern "C" void kernel_launch(void* const* d_in, const int* in_sizes, int n_in,
                              void* d_out, int out_size) {
    const float* x   = (const float*)d_in[0];
    const void*  ei  = d_in[1];
    const float* ew  = (const float*)d_in[2];
    const float* Wg  = (const float*)d_in[3];
    const float* bg  = (const float*)d_in[4];
    const float* Wt  = (const float*)d_in[5];
    const float* btm = (const float*)d_in[6];
    const float* lnw = (const float*)d_in[7];
    const float* lnb = (const float*)d_in[8];
    const float* Wr  = (const float*)d_in[9];
    const float* br  = (const float*)d_in[10];
    float* out = (float*)d_out;

    k_inproj  <<<1000, 128>>>(x, Wg, Wr, br);          // #1
    p_deg     <<<63 + 384, 128>>>(ei, ew, Wt);         // #2
    p_scanfill<<<1, 512>>>(ei, ew);                    // #3
    k_gcn     <<<dim3(BT, 8), 128>>>(bg);              // #4  <- profiled
    k_conv    <<<4000, 128>>>(btm, lnw, lnb, out);     // #5
}

// round 14
// speedup vs baseline: 1.0888x; 1.0766x over previous
#include <cuda_runtime.h>
#include <math.h>

#define Bv  8
#define Tv  32
#define Nv  500
#define Fv  64
#define Hv  128
#define Ev  8000
#define BT  256            // B*T
#define BTN 128000         // B*T*N
#define NNZ (Ev + Nv)

// ---------------- scratch (static device globals: allowed) ----------------
__device__ float  g_xf [BTN * Hv];   // x @ W_gcn            (bt, n, h)
__device__ float  g_res[BTN * Hv];   // x @ W_res + b_res    (bt, n, h)
__device__ float  g_hg [BTN * Hv];   // gelu(gcn agg + b)    (bt, n, h)
__device__ float  g_wt [384 * Hv];   // W_temp transposed: [(i*3+k)][o]
__device__ float  g_deg [Nv];        // zero-init (BSS); re-zeroed each run
__device__ int    g_cnt [Nv];        // zero-init (BSS); re-zeroed each run
__device__ int    g_rowptr[Nv + 1];
__device__ float2 g_ev[NNZ];         // {norm, __int_as_float(src)} CSR by dst

// ---------------- helpers ----------------
__device__ __forceinline__ unsigned long long pack2(float lo, float hi) {
    unsigned long long r;
    asm("mov.b64 %0, {%1, %2};" : "=l"(r) : "f"(lo), "f"(hi));
    return r;
}
__device__ __forceinline__ void unpack2(unsigned long long v, float& lo, float& hi) {
    asm("mov.b64 {%0, %1}, %2;" : "=f"(lo), "=f"(hi) : "l"(v));
}
__device__ __forceinline__ void fma2(unsigned long long& d, unsigned long long a,
                                     unsigned long long b) {
    asm("fma.rn.f32x2 %0, %1, %2, %0;" : "+l"(d) : "l"(a), "l"(b));
}
__device__ __forceinline__ float gelu_exact(float x) {
    return 0.5f * x * (1.0f + erff(x * 0.7071067811865476f));
}
__device__ __forceinline__ int detect64(const void* ei) {
    const long long* p = (const long long*)ei;
    int ok64 = 1;
#pragma unroll
    for (int j = 0; j < 8; ++j) {
        long long v = p[j];
        if (v < 0 || v >= Nv) ok64 = 0;
    }
    return ok64;
}
__device__ __forceinline__ int load_idx(const void* ei, int i, int is64) {
    long long v;
    if (is64) v = ((const long long*)ei)[i];
    else      v = ((const int*)ei)[i];
    if (v < 0) v = 0;
    if (v >= Nv) v = Nv - 1;
    return (int)v;
}

// ---------------- K2 (launch #1): fused input projections, f32x2 packed ---
__global__ __launch_bounds__(128) void k_inproj(
    const float* __restrict__ x, const float* __restrict__ Wg,
    const float* __restrict__ Wr, const float* __restrict__ br) {
    __shared__ float sx[8][64];
    int h = threadIdx.x;
    unsigned long long wp[64];
#pragma unroll
    for (int i = 0; i < 64; ++i) wp[i] = pack2(Wg[i * Hv + h], Wr[i * Hv + h]);
    float brh = br[h];
    int row0 = blockIdx.x * 128;
#pragma unroll 1
    for (int c = 0; c < 16; ++c) {
        int rbase = row0 + c * 8;
        __syncthreads();
        for (int j = h; j < 512; j += 128)
            sx[j >> 6][j & 63] = x[(rbase + (j >> 6)) * Fv + (j & 63)];
        __syncthreads();
#pragma unroll
        for (int r = 0; r < 8; ++r) {
            unsigned long long acc = 0ULL;
#pragma unroll
            for (int i = 0; i < 64; i += 4) {
                float4 xv = *(const float4*)&sx[r][i];
                fma2(acc, pack2(xv.x, xv.x), wp[i + 0]);
                fma2(acc, pack2(xv.y, xv.y), wp[i + 1]);
                fma2(acc, pack2(xv.z, xv.z), wp[i + 2]);
                fma2(acc, pack2(xv.w, xv.w), wp[i + 3]);
            }
            float ag, ar; unpack2(acc, ag, ar);
            int row = rbase + r;
            g_xf [row * Hv + h] = ag;
            g_res[row * Hv + h] = ar + brh;
        }
    }
}

// ---------------- P1 (launch #2): degree + counts; tail blocks wtrans -----
__global__ void p_deg(const void* __restrict__ ei, const float* __restrict__ ew,
                      const float* __restrict__ Wt) {
    if (blockIdx.x >= 63) {
        int idx = (blockIdx.x - 63) * 128 + threadIdx.x;   // < 49152
        if (idx < 128 * 384) {
            int o = idx / 384, m = idx % 384;
            g_wt[m * Hv + o] = Wt[o * 384 + m];
        }
        return;
    }
    __shared__ int sis64;
    if (threadIdx.x == 0) sis64 = detect64(ei);
    __syncthreads();
    int is64 = sis64;
    int e = blockIdx.x * 128 + threadIdx.x;
    if (e >= Ev) return;
    int dst = load_idx(ei, Ev + e, is64);
    atomicAdd(&g_deg[dst], ew[e]);
    atomicAdd(&g_cnt[dst], 1);
}

// ---------------- P2 (launch #3): scan + CSR fill, single block -----------
__global__ __launch_bounds__(512) void p_scanfill(
    const void* __restrict__ ei, const float* __restrict__ ew) {
    __shared__ int   s[512];
    __shared__ float sdinv[Nv];
    __shared__ int   sfill[Nv];
    __shared__ int   sis64;
    int tid = threadIdx.x;
    if (tid == 0) sis64 = detect64(ei);

    int c = 0;
    if (tid < Nv) {
        float d = g_deg[tid] + 1.0f;           // + self loop weight
        sdinv[tid] = rsqrtf(d);
        c = g_cnt[tid] + 1;                    // + self loop edge
    }
    s[tid] = c;
    __syncthreads();
    for (int off = 1; off < 512; off <<= 1) {
        int v = (tid >= off) ? s[tid - off] : 0;
        __syncthreads();
        s[tid] += v;
        __syncthreads();
    }
    if (tid < Nv) {
        g_rowptr[tid + 1] = s[tid];
        sfill[tid] = s[tid] - c;
        if (tid == 0) g_rowptr[0] = 0;
        g_deg[tid] = 0.0f;                     // reset for next graph replay
        g_cnt[tid] = 0;
    }
    __syncthreads();
    int is64 = sis64;
    for (int e = tid; e < NNZ; e += 512) {
        int src, dst; float w;
        if (e < Ev) { src = load_idx(ei, e, is64); dst = load_idx(ei, Ev + e, is64); w = ew[e]; }
        else        { src = dst = e - Ev; w = 1.0f; }
        float v = sdinv[src] * w * sdinv[dst];
        int pos = atomicAdd(&sfill[dst], 1);
        if (pos >= 0 && pos < NNZ)
            g_ev[pos] = make_float2(v, __int_as_float(src));
    }
}

// ---------------- K3 (launch #4, PROFILED): GCN v5 channel-quad gather ----
// 16 channels/block as float4[500][4] (32KB). Each thread owns 4 channels of
// a dst row: per edge = 1 LDG.64 + 1 IMAD + 1 LDS.128 + 2 FFMA2 (4 MACs).
__global__ __launch_bounds__(128) void k_gcn(const float* __restrict__ bg) {
    __shared__ __align__(16) float4 sxf4[Nv * 4];   // 32000 B
    int bt = blockIdx.x;
    int hbase = blockIdx.y * 16;
    int tid = threadIdx.x;
    const float4* xsrc4 = (const float4*)(g_xf + (size_t)bt * (Nv * Hv));
    int c4base = hbase >> 2;
    for (int idx = tid; idx < Nv * 4; idx += 128) {
        int n = idx >> 2, c4 = idx & 3;
        sxf4[idx] = xsrc4[n * 32 + c4base + c4];
    }
    __syncthreads();
    int hh4 = tid & 3;               // channel quad within tile
    int ns = tid >> 2;               // 0..31
    int ch = hbase + 4 * hh4;
    float4 bgv = *(const float4*)(bg + ch);
    float4* dst4 = (float4*)(g_hg + (size_t)bt * (Nv * Hv));
    const ulonglong2* sxp = (const ulonglong2*)sxf4;
    for (int n = ns; n < Nv; n += 32) {
        int rs = g_rowptr[n], re = g_rowptr[n + 1];
        unsigned long long accA = 0ULL, accB = 0ULL;
        int e = rs;
        for (; e + 1 < re; e += 2) {
            float2 ev0 = g_ev[e];
            float2 ev1 = g_ev[e + 1];
            ulonglong2 v0 = sxp[__float_as_int(ev0.y) * 4 + hh4];
            ulonglong2 v1 = sxp[__float_as_int(ev1.y) * 4 + hh4];
            unsigned long long w0 = pack2(ev0.x, ev0.x);
            unsigned long long w1 = pack2(ev1.x, ev1.x);
            fma2(accA, w0, v0.x);
            fma2(accB, w0, v0.y);
            fma2(accA, w1, v1.x);
            fma2(accB, w1, v1.y);
        }
        if (e < re) {
            float2 ev0 = g_ev[e];
            ulonglong2 v0 = sxp[__float_as_int(ev0.y) * 4 + hh4];
            unsigned long long w0 = pack2(ev0.x, ev0.x);
            fma2(accA, w0, v0.x);
            fma2(accB, w0, v0.y);
        }
        float a0, a1, a2, a3;
        unpack2(accA, a0, a1);
        unpack2(accB, a2, a3);
        float4 r;
        r.x = gelu_exact(a0 + bgv.x);
        r.y = gelu_exact(a1 + bgv.y);
        r.z = gelu_exact(a2 + bgv.z);
        r.w = gelu_exact(a3 + bgv.w);
        dst4[n * 32 + (ch >> 2)] = r;
    }
}

// ---------------- K4 (launch #5): conv + gelu + residual + LayerNorm ------
// v4 (R11 best): ONE (b,n) per block; t-dim packed into f32x2 lanes (t, t+16).
__global__ __launch_bounds__(128) void k_conv(
    const float* __restrict__ btmp,
    const float* __restrict__ lnw, const float* __restrict__ lnb,
    float* __restrict__ out) {
    __shared__ __align__(16) char smbuf[18432];
    __shared__ float smu[32], srs[32];
    int o = threadIdx.x;
    int bn = blockIdx.x;
    int b = bn / Nv, n = bn % Nv;

    // ---- stage packed input pairs ----
    {
        float xv[32];
        const float* src = g_hg + ((size_t)(b * Tv) * Nv + n) * Hv + o;
#pragma unroll
        for (int t = 0; t < 32; ++t) xv[t] = src[(size_t)t * Nv * Hv];
        float2* sp = (float2*)smbuf;          // [s][128]
#pragma unroll
        for (int s = 0; s < 18; ++s) {
            float lo = (s == 0)  ? 0.0f : xv[s - 1];
            float hi = (s == 17) ? 0.0f : xv[s + 15];
            sp[s * 128 + o] = make_float2(lo, hi);
        }
    }
    __syncthreads();

    unsigned long long acc[16];
#pragma unroll
    for (int t = 0; t < 16; ++t) acc[t] = 0ULL;

    const float* wtp = g_wt + o;               // [(m)][o], lane-coalesced
    const ulonglong2* colbase = (const ulonglong2*)smbuf;   // [s][64]
#pragma unroll 1
    for (int q = 0; q < 64; ++q) {             // i = 2q, 2q+1
        int m = q * 6;
        float wa0 = wtp[(m + 0) * Hv];
        float wa1 = wtp[(m + 1) * Hv];
        float wa2 = wtp[(m + 2) * Hv];
        float wb0 = wtp[(m + 3) * Hv];
        float wb1 = wtp[(m + 4) * Hv];
        float wb2 = wtp[(m + 5) * Hv];
        unsigned long long w0a = pack2(wa0, wa0), w1a = pack2(wa1, wa1),
                           w2a = pack2(wa2, wa2);
        unsigned long long w0b = pack2(wb0, wb0), w1b = pack2(wb1, wb1),
                           w2b = pack2(wb2, wb2);
        const ulonglong2* col = colbase + q;    // stride 64 per s
        ulonglong2 v0 = col[0];                 // s = t + kk
        ulonglong2 v1 = col[64];
#pragma unroll
        for (int t = 0; t < 16; ++t) {
            ulonglong2 v2 = col[(t + 2) * 64];
            fma2(acc[t], w0a, v0.x);
            fma2(acc[t], w0b, v0.y);
            fma2(acc[t], w1a, v1.x);
            fma2(acc[t], w1b, v1.y);
            fma2(acc[t], w2a, v2.x);
            fma2(acc[t], w2b, v2.y);
            v0 = v1; v1 = v2;
        }
    }
    __syncthreads();   // done reading p; reuse smbuf as y[32][129]

    float btv = btmp[o];
    float* shy = (float*)smbuf;
    {
        const float* resp = g_res + ((size_t)(b * Tv) * Nv + n) * Hv + o;
#pragma unroll
        for (int t = 0; t < 16; ++t) {
            float y0, y1; unpack2(acc[t], y0, y1);
            float h0 = gelu_exact(y0 + btv) + resp[(size_t)t * Nv * Hv];
            float h1 = gelu_exact(y1 + btv) + resp[(size_t)(t + 16) * Nv * Hv];
            shy[t * 129 + o] = h0;
            shy[(t + 16) * 129 + o] = h1;
        }
    }
    __syncthreads();

    if (o < 32) {
        int r = o;
        float s1 = 0.0f;
#pragma unroll 8
        for (int j = 0; j < 128; ++j) s1 += shy[r * 129 + j];
        float mu = s1 * (1.0f / 128.0f);
        float s2 = 0.0f;
#pragma unroll 8
        for (int j = 0; j < 128; ++j) {
            float d = shy[r * 129 + j] - mu;
            s2 += d * d;
        }
        smu[r] = mu;
        srs[r] = rsqrtf(s2 * (1.0f / 128.0f) + 1e-5f);
    }
    __syncthreads();

    float lw = lnw[o], lb = lnb[o];
    float* op = out + ((size_t)(b * Tv) * Nv + n) * Hv + o;
#pragma unroll
    for (int t = 0; t < 32; ++t) {
        float v = shy[t * 129 + o];
        op[(size_t)t * Nv * Hv] = (v - smu[t]) * srs[t] * lw + lb;
    }
}

// ---------------- launch ----------------
extern "C" void kernel_launch(void* const* d_in, const int* in_sizes, int n_in,
                              void* d_out, int out_size) {
    const float* x   = (const float*)d_in[0];
    const void*  ei  = d_in[1];
    const float* ew  = (const float*)d_in[2];
    const float* Wg  = (const float*)d_in[3];
    const float* bg  = (const float*)d_in[4];
    const float* Wt  = (const float*)d_in[5];
    const float* btm = (const float*)d_in[6];
    const float* lnw = (const float*)d_in[7];
    const float* lnb = (const float*)d_in[8];
    const float* Wr  = (const float*)d_in[9];
    const float* br  = (const float*)d_in[10];
    float* out = (float*)d_out;

    k_inproj  <<<1000, 128>>>(x, Wg, Wr, br);          // #1
    p_deg     <<<63 + 384, 128>>>(ei, ew, Wt);         // #2
    p_scanfill<<<1, 512>>>(ei, ew);                    // #3
    k_gcn     <<<dim3(BT, 8), 128>>>(bg);              // #4  <- profiled
    k_conv    <<<4000, 128>>>(btm, lnw, lnb, out);     // #5
}